// round 6
// baseline (speedup 1.0000x reference)
#include <cuda_runtime.h>

#define BATCH 64
#define SEQ   1024
#define DIM   1280
#define H1    640
#define H2    320

#define CHUNK      16         // rows per work item
#define MAXCH      64         // max chunks per batch (1022/16 -> 64)
#define PGRID      296        // pool blocks (2 per SM)
#define KS1        8          // k-splits for GEMM1 (1280/8 = 160)
#define KS2        4          // k-splits for GEMM2 (640/4  = 160)
#define KR         160        // k-range per split (both gemms)
#define JT         32         // output-column tile
#define KT         32         // k chunk staged in smem
#define SP_STRIDE  33         // padded smem stride (bank-conflict free)

// Scratch (written fully every launch for all slots that are later read;
// no atomics, deterministic)
__device__ float g_poolp[BATCH * MAXCH * DIM]; // per-chunk partial sums (~21MB)
__device__ float g_pooled[BATCH * DIM];        // reduced & scaled pooled rep
__device__ float g_z1p[KS1][BATCH * H1];       // layer-1 pre-act partials
__device__ float g_z2p[KS2][BATCH * H2];       // layer-2 pre-act partials

// ---------------------------------------------------------------------------
// Pool: globally balanced. Work item = (batch, 16-row chunk) over the REAL
// row range [1, len-1). Items enumerated compactly via prefix sum; blocks
// stride the item list -> every block gets ~T/PGRID items of identical size.
// 320 threads; thread owns one float4 column.
// ---------------------------------------------------------------------------
__global__ void pool_kernel(const float* __restrict__ rep,
                            const int* __restrict__ blen) {
    __shared__ int pre[BATCH + 1];
    __shared__ int sn[BATCH];

    const int t = threadIdx.x;
    if (t < BATCH) {
        int n = blen[t] - 2;                  // rows in [1, len-1), >= 1
        sn[t] = n;
    }
    __syncthreads();
    if (t == 0) {
        int s = 0;
        for (int i = 0; i < BATCH; ++i) {
            pre[i] = s;
            s += (sn[i] + CHUNK - 1) / CHUNK;
        }
        pre[BATCH] = s;
    }
    __syncthreads();
    const int T = pre[BATCH];
    const int row4 = DIM / 4;

    for (int item = blockIdx.x; item < T; item += gridDim.x) {
        // binary search: b with pre[b] <= item < pre[b+1] (uniform per block)
        int lo = 0, hi = BATCH;
        while (hi - lo > 1) {
            int mid = (lo + hi) >> 1;
            if (pre[mid] <= item) lo = mid; else hi = mid;
        }
        const int b  = lo;
        const int ch = item - pre[b];
        const int l0 = 1 + ch * CHUNK;
        int l1 = 1 + sn[b];
        if (l1 > l0 + CHUNK) l1 = l0 + CHUNK;

        const float4* base =
            reinterpret_cast<const float4*>(rep + (size_t)b * SEQ * DIM) + t;

        float4 acc = make_float4(0.f, 0.f, 0.f, 0.f);
        int l = l0;
        for (; l + 3 < l1; l += 4) {
            float4 a0 = base[(size_t)(l + 0) * row4];
            float4 a1 = base[(size_t)(l + 1) * row4];
            float4 a2 = base[(size_t)(l + 2) * row4];
            float4 a3 = base[(size_t)(l + 3) * row4];
            acc.x += (a0.x + a1.x) + (a2.x + a3.x);
            acc.y += (a0.y + a1.y) + (a2.y + a3.y);
            acc.z += (a0.z + a1.z) + (a2.z + a3.z);
            acc.w += (a0.w + a1.w) + (a2.w + a3.w);
        }
        for (; l < l1; ++l) {
            float4 a = base[(size_t)l * row4];
            acc.x += a.x; acc.y += a.y; acc.z += a.z; acc.w += a.w;
        }
        reinterpret_cast<float4*>(
            g_poolp + (size_t)((b << 6) + ch) * DIM)[t] = acc;
    }
}

// ---------------------------------------------------------------------------
// Reduce: pooled[b][d] = (sum over real chunks of partials) / count.
// grid 64, 320 threads; thread owns one float4 column. L2-resident reads.
// ---------------------------------------------------------------------------
__global__ void reduce_kernel(const int* __restrict__ blen) {
    const int b = blockIdx.x;
    const int t = threadIdx.x;
    int n = blen[b] - 2; if (n < 1) n = 1;
    const int c  = (n + CHUNK - 1) / CHUNK;
    const float rc = 1.0f / (float)n;
    const int row4 = DIM / 4;

    const float4* src =
        reinterpret_cast<const float4*>(g_poolp + (size_t)(b << 6) * DIM) + t;

    float4 acc = make_float4(0.f, 0.f, 0.f, 0.f);
    int ch = 0;
    for (; ch + 3 < c; ch += 4) {
        float4 a0 = src[(size_t)(ch + 0) * row4];
        float4 a1 = src[(size_t)(ch + 1) * row4];
        float4 a2 = src[(size_t)(ch + 2) * row4];
        float4 a3 = src[(size_t)(ch + 3) * row4];
        acc.x += (a0.x + a1.x) + (a2.x + a3.x);
        acc.y += (a0.y + a1.y) + (a2.y + a3.y);
        acc.z += (a0.z + a1.z) + (a2.z + a3.z);
        acc.w += (a0.w + a1.w) + (a2.w + a3.w);
    }
    for (; ch < c; ++ch) {
        float4 a = src[(size_t)ch * row4];
        acc.x += a.x; acc.y += a.y; acc.z += a.z; acc.w += a.w;
    }
    acc.x *= rc; acc.y *= rc; acc.z *= rc; acc.w *= rc;
    reinterpret_cast<float4*>(g_pooled + (size_t)b * DIM)[t] = acc;
}

// ---------------------------------------------------------------------------
// GEMM1: z1 += pooled @ W1   (partials per k-split)
// grid (20 j-tiles, 8 k-splits), 128 threads.
// Thread: jq = t&7 -> 4 cols, bq = t>>3 -> 4 batches => 4x4 register tile.
// ---------------------------------------------------------------------------
__global__ void gemm1_kernel(const float* __restrict__ W1) {
    __shared__ float sW[KT * JT];
    __shared__ float sP[BATCH * SP_STRIDE];

    const int t  = threadIdx.x;
    const int j0 = blockIdx.x * JT;
    const int k0 = blockIdx.y * KR;
    const int jq = t & 7;
    const int bq = t >> 3;

    float acc[4][4] = {};

    for (int kc = 0; kc < KR; kc += KT) {
        __syncthreads();
        // stage W1 tile [KT][JT]
#pragma unroll
        for (int r = 0; r < (KT * JT) / 128; ++r) {
            int e  = r * 128 + t;
            int kk = e >> 5, jj = e & 31;
            sW[e] = W1[(size_t)(k0 + kc + kk) * H1 + j0 + jj];
        }
        // stage pooled tile [BATCH][KT]
#pragma unroll
        for (int r = 0; r < (BATCH * KT) / 128; ++r) {
            int e  = r * 128 + t;
            int b  = e >> 5, kk = e & 31;
            sP[b * SP_STRIDE + kk] = g_pooled[b * DIM + k0 + kc + kk];
        }
        __syncthreads();
#pragma unroll
        for (int kk = 0; kk < KT; ++kk) {
            float4 w = *reinterpret_cast<const float4*>(&sW[kk * JT + jq * 4]);
#pragma unroll
            for (int i = 0; i < 4; ++i) {
                float p = sP[(bq * 4 + i) * SP_STRIDE + kk];
                acc[i][0] += p * w.x; acc[i][1] += p * w.y;
                acc[i][2] += p * w.z; acc[i][3] += p * w.w;
            }
        }
    }

    float* zp = g_z1p[blockIdx.y];
#pragma unroll
    for (int i = 0; i < 4; ++i) {
        int b = bq * 4 + i;
#pragma unroll
        for (int jj = 0; jj < 4; ++jj)
            zp[b * H1 + j0 + jq * 4 + jj] = acc[i][jj];
    }
}

// ---------------------------------------------------------------------------
// GEMM2: z2 += relu(z1 + b1) @ W2   (partials per k-split)
// grid (10 j-tiles, 4 k-splits), 128 threads. Same tiling as GEMM1.
// ---------------------------------------------------------------------------
__global__ void gemm2_kernel(const float* __restrict__ W2,
                             const float* __restrict__ b1) {
    __shared__ float sW[KT * JT];
    __shared__ float sP[BATCH * SP_STRIDE];

    const int t  = threadIdx.x;
    const int j0 = blockIdx.x * JT;
    const int k0 = blockIdx.y * KR;
    const int jq = t & 7;
    const int bq = t >> 3;

    float acc[4][4] = {};

    for (int kc = 0; kc < KR; kc += KT) {
        __syncthreads();
#pragma unroll
        for (int r = 0; r < (KT * JT) / 128; ++r) {
            int e  = r * 128 + t;
            int kk = e >> 5, jj = e & 31;
            sW[e] = W2[(size_t)(k0 + kc + kk) * H2 + j0 + jj];
        }
#pragma unroll
        for (int r = 0; r < (BATCH * KT) / 128; ++r) {
            int e  = r * 128 + t;
            int b  = e >> 5, kk = e & 31;
            int k  = k0 + kc + kk;
            int gi = b * H1 + k;
            float z = 0.f;
#pragma unroll
            for (int s = 0; s < KS1; ++s) z += g_z1p[s][gi];
            z += b1[k];
            sP[b * SP_STRIDE + kk] = fmaxf(z, 0.f);
        }
        __syncthreads();
#pragma unroll
        for (int kk = 0; kk < KT; ++kk) {
            float4 w = *reinterpret_cast<const float4*>(&sW[kk * JT + jq * 4]);
#pragma unroll
            for (int i = 0; i < 4; ++i) {
                float p = sP[(bq * 4 + i) * SP_STRIDE + kk];
                acc[i][0] += p * w.x; acc[i][1] += p * w.y;
                acc[i][2] += p * w.z; acc[i][3] += p * w.w;
            }
        }
    }

    float* zp = g_z2p[blockIdx.y];
#pragma unroll
    for (int i = 0; i < 4; ++i) {
        int b = bq * 4 + i;
#pragma unroll
        for (int jj = 0; jj < 4; ++jj)
            zp[b * H2 + j0 + jq * 4 + jj] = acc[i][jj];
    }
}

// ---------------------------------------------------------------------------
// Final: one block per batch (64 blocks, 320 threads). Thread t owns k=t:
//   emb[b,k] = relu(sum_s z2p[s] + b2[k])  -> out[128 + b*320 + k]
//   y[b,o]   = sum_k emb[b,k]*W3[k,o] + b3 -> out[b*2 + o]  (block reduction)
// ---------------------------------------------------------------------------
__global__ void final_kernel(const float* __restrict__ b2,
                             const float* __restrict__ W3,
                             const float* __restrict__ b3,
                             float* __restrict__ out) {
    const int b = blockIdx.x;
    const int k = threadIdx.x;            // 0..319
    const int gi = b * H2 + k;

    float z = 0.f;
#pragma unroll
    for (int s = 0; s < KS2; ++s) z += g_z2p[s][gi];
    float e = fmaxf(z + b2[k], 0.f);
    out[BATCH * 2 + gi] = e;

    float2 w = *reinterpret_cast<const float2*>(&W3[k * 2]);
    float p0 = e * w.x;
    float p1 = e * w.y;

    // warp reduce
#pragma unroll
    for (int off = 16; off > 0; off >>= 1) {
        p0 += __shfl_down_sync(0xFFFFFFFFu, p0, off);
        p1 += __shfl_down_sync(0xFFFFFFFFu, p1, off);
    }
    __shared__ float s0[10], s1[10];
    const int wid = k >> 5, lid = k & 31;
    if (lid == 0) { s0[wid] = p0; s1[wid] = p1; }
    __syncthreads();
    if (k == 0) {
        float a0 = 0.f, a1 = 0.f;
#pragma unroll
        for (int wi = 0; wi < 10; ++wi) { a0 += s0[wi]; a1 += s1[wi]; }
        out[b * 2 + 0] = a0 + b3[0];
        out[b * 2 + 1] = a1 + b3[1];
    }
}

// ---------------------------------------------------------------------------
extern "C" void kernel_launch(void* const* d_in, const int* in_sizes, int n_in,
                              void* d_out, int out_size) {
    const float* rep  = (const float*)d_in[0];
    const int*   blen = (const int*)  d_in[1];
    const float* W1   = (const float*)d_in[2];
    const float* b1   = (const float*)d_in[3];
    const float* W2   = (const float*)d_in[4];
    const float* b2   = (const float*)d_in[5];
    const float* W3   = (const float*)d_in[6];
    const float* b3   = (const float*)d_in[7];
    float* out = (float*)d_out;

    pool_kernel  <<<PGRID, 320>>>(rep, blen);
    reduce_kernel<<<BATCH, 320>>>(blen);
    gemm1_kernel <<<dim3(H1 / JT, KS1), 128>>>(W1);
    gemm2_kernel <<<dim3(H2 / JT, KS2), 128>>>(W2, b1);
    final_kernel <<<BATCH, H2>>>(b2, W3, b3, out);
}

// round 7
// speedup vs baseline: 1.1199x; 1.1199x over previous
#include <cuda_runtime.h>

#define BATCH 64
#define SEQ   1024
#define DIM   1280
#define H1    640
#define H2    320

#define CHUNK      16         // rows per pool work item
#define MAXCH      64         // max chunks per batch
#define PGRID      296        // pool blocks (2 per SM)
#define KS1        8          // k-splits for GEMM1 (1280/8 = 160)
#define KS2        4          // k-splits for GEMM2 (640/4  = 160)
#define KR         160        // k-range per split (both gemms)
#define JT         32         // output-column tile
#define KT         32         // k chunk staged in smem
#define SP_STRIDE  33         // padded smem stride (bank-conflict free)

// Scratch (all slots later read are written every launch; no atomics)
__device__ float g_poolp[BATCH * MAXCH * DIM]; // per-chunk partial sums
__device__ float g_pooled[BATCH * DIM];        // reduced & scaled pooled rep
__device__ float g_z1p[KS1][BATCH * H1];       // layer-1 pre-act partials
__device__ float g_z1[BATCH * H1];             // relu(z1+b1) final
__device__ float g_z2p[KS2][BATCH * H2];       // layer-2 pre-act partials

// ---------------------------------------------------------------------------
// Pool: globally balanced 16-row chunks over [1, len-1), compact item list.
// ---------------------------------------------------------------------------
__global__ void pool_kernel(const float* __restrict__ rep,
                            const int* __restrict__ blen) {
    __shared__ int pre[BATCH + 1];
    __shared__ int sn[BATCH];

    const int t = threadIdx.x;
    if (t < BATCH) sn[t] = blen[t] - 2;          // rows in [1, len-1), >= 1
    __syncthreads();
    if (t == 0) {
        int s = 0;
        for (int i = 0; i < BATCH; ++i) {
            pre[i] = s;
            s += (sn[i] + CHUNK - 1) / CHUNK;
        }
        pre[BATCH] = s;
    }
    __syncthreads();
    const int T = pre[BATCH];
    const int row4 = DIM / 4;

    for (int item = blockIdx.x; item < T; item += gridDim.x) {
        int lo = 0, hi = BATCH;
        while (hi - lo > 1) {
            int mid = (lo + hi) >> 1;
            if (pre[mid] <= item) lo = mid; else hi = mid;
        }
        const int b  = lo;
        const int ch = item - pre[b];
        const int l0 = 1 + ch * CHUNK;
        int l1 = 1 + sn[b];
        if (l1 > l0 + CHUNK) l1 = l0 + CHUNK;

        const float4* base =
            reinterpret_cast<const float4*>(rep + (size_t)b * SEQ * DIM) + t;

        float4 acc = make_float4(0.f, 0.f, 0.f, 0.f);
        int l = l0;
        for (; l + 3 < l1; l += 4) {
            float4 a0 = base[(size_t)(l + 0) * row4];
            float4 a1 = base[(size_t)(l + 1) * row4];
            float4 a2 = base[(size_t)(l + 2) * row4];
            float4 a3 = base[(size_t)(l + 3) * row4];
            acc.x += (a0.x + a1.x) + (a2.x + a3.x);
            acc.y += (a0.y + a1.y) + (a2.y + a3.y);
            acc.z += (a0.z + a1.z) + (a2.z + a3.z);
            acc.w += (a0.w + a1.w) + (a2.w + a3.w);
        }
        for (; l < l1; ++l) {
            float4 a = base[(size_t)l * row4];
            acc.x += a.x; acc.y += a.y; acc.z += a.z; acc.w += a.w;
        }
        reinterpret_cast<float4*>(
            g_poolp + (size_t)((b << 6) + ch) * DIM)[t] = acc;
    }
}

// ---------------------------------------------------------------------------
// Reduce pool: pooled[b][d] = (sum over real chunks) / count. grid 64 x 320.
// ---------------------------------------------------------------------------
__global__ void reduce_kernel(const int* __restrict__ blen) {
    const int b = blockIdx.x;
    const int t = threadIdx.x;
    int n = blen[b] - 2; if (n < 1) n = 1;
    const int c  = (n + CHUNK - 1) / CHUNK;
    const float rc = 1.0f / (float)n;
    const int row4 = DIM / 4;

    const float4* src =
        reinterpret_cast<const float4*>(g_poolp + (size_t)(b << 6) * DIM) + t;

    float4 acc = make_float4(0.f, 0.f, 0.f, 0.f);
    int ch = 0;
    for (; ch + 3 < c; ch += 4) {
        float4 a0 = src[(size_t)(ch + 0) * row4];
        float4 a1 = src[(size_t)(ch + 1) * row4];
        float4 a2 = src[(size_t)(ch + 2) * row4];
        float4 a3 = src[(size_t)(ch + 3) * row4];
        acc.x += (a0.x + a1.x) + (a2.x + a3.x);
        acc.y += (a0.y + a1.y) + (a2.y + a3.y);
        acc.z += (a0.z + a1.z) + (a2.z + a3.z);
        acc.w += (a0.w + a1.w) + (a2.w + a3.w);
    }
    for (; ch < c; ++ch) {
        float4 a = src[(size_t)ch * row4];
        acc.x += a.x; acc.y += a.y; acc.z += a.z; acc.w += a.w;
    }
    acc.x *= rc; acc.y *= rc; acc.z *= rc; acc.w *= rc;
    reinterpret_cast<float4*>(g_pooled + (size_t)b * DIM)[t] = acc;
}

// ---------------------------------------------------------------------------
// GEMM1: z1p[split] = pooled @ W1 slice. grid (20, 8), 128 threads.
// Staging is now single independent loads (no in-loop reductions).
// ---------------------------------------------------------------------------
__global__ void gemm1_kernel(const float* __restrict__ W1) {
    __shared__ float sW[KT * JT];
    __shared__ float sP[BATCH * SP_STRIDE];

    const int t  = threadIdx.x;
    const int j0 = blockIdx.x * JT;
    const int k0 = blockIdx.y * KR;
    const int jq = t & 7;
    const int bq = t >> 3;

    float acc[4][4] = {};

    for (int kc = 0; kc < KR; kc += KT) {
        __syncthreads();
#pragma unroll
        for (int r = 0; r < (KT * JT) / 128; ++r) {
            int e  = r * 128 + t;
            int kk = e >> 5, jj = e & 31;
            sW[e] = W1[(size_t)(k0 + kc + kk) * H1 + j0 + jj];
        }
#pragma unroll
        for (int r = 0; r < (BATCH * KT) / 128; ++r) {
            int e  = r * 128 + t;
            int b  = e >> 5, kk = e & 31;
            sP[b * SP_STRIDE + kk] = g_pooled[b * DIM + k0 + kc + kk];
        }
        __syncthreads();
#pragma unroll
        for (int kk = 0; kk < KT; ++kk) {
            float4 w = *reinterpret_cast<const float4*>(&sW[kk * JT + jq * 4]);
#pragma unroll
            for (int i = 0; i < 4; ++i) {
                float p = sP[(bq * 4 + i) * SP_STRIDE + kk];
                acc[i][0] += p * w.x; acc[i][1] += p * w.y;
                acc[i][2] += p * w.z; acc[i][3] += p * w.w;
            }
        }
    }

    float* zp = g_z1p[blockIdx.y];
#pragma unroll
    for (int i = 0; i < 4; ++i) {
        int b = bq * 4 + i;
#pragma unroll
        for (int jj = 0; jj < 4; ++jj)
            zp[b * H1 + j0 + jq * 4 + jj] = acc[i][jj];
    }
}

// ---------------------------------------------------------------------------
// Relu-reduce z1: z1[i] = relu(sum_{s<8} z1p[s][i] + b1[i % H1]).
// grid 40 x 1024 — one element per thread, 8 independent L2 loads (MLP=8).
// ---------------------------------------------------------------------------
__global__ void relu_z1_kernel(const float* __restrict__ b1) {
    const int i = blockIdx.x * 1024 + threadIdx.x;   // < 40960 always
    float z = 0.f;
#pragma unroll
    for (int s = 0; s < KS1; ++s) z += g_z1p[s][i];
    g_z1[i] = fmaxf(z + b1[i % H1], 0.f);
}

// ---------------------------------------------------------------------------
// GEMM2: z2p[split] = z1 @ W2 slice. grid (10, 4), 128 threads.
// Staging is single loads from final g_z1.
// ---------------------------------------------------------------------------
__global__ void gemm2_kernel(const float* __restrict__ W2) {
    __shared__ float sW[KT * JT];
    __shared__ float sP[BATCH * SP_STRIDE];

    const int t  = threadIdx.x;
    const int j0 = blockIdx.x * JT;
    const int k0 = blockIdx.y * KR;
    const int jq = t & 7;
    const int bq = t >> 3;

    float acc[4][4] = {};

    for (int kc = 0; kc < KR; kc += KT) {
        __syncthreads();
#pragma unroll
        for (int r = 0; r < (KT * JT) / 128; ++r) {
            int e  = r * 128 + t;
            int kk = e >> 5, jj = e & 31;
            sW[e] = W2[(size_t)(k0 + kc + kk) * H2 + j0 + jj];
        }
#pragma unroll
        for (int r = 0; r < (BATCH * KT) / 128; ++r) {
            int e  = r * 128 + t;
            int b  = e >> 5, kk = e & 31;
            sP[b * SP_STRIDE + kk] = g_z1[b * H1 + k0 + kc + kk];
        }
        __syncthreads();
#pragma unroll
        for (int kk = 0; kk < KT; ++kk) {
            float4 w = *reinterpret_cast<const float4*>(&sW[kk * JT + jq * 4]);
#pragma unroll
            for (int i = 0; i < 4; ++i) {
                float p = sP[(bq * 4 + i) * SP_STRIDE + kk];
                acc[i][0] += p * w.x; acc[i][1] += p * w.y;
                acc[i][2] += p * w.z; acc[i][3] += p * w.w;
            }
        }
    }

    float* zp = g_z2p[blockIdx.y];
#pragma unroll
    for (int i = 0; i < 4; ++i) {
        int b = bq * 4 + i;
#pragma unroll
        for (int jj = 0; jj < 4; ++jj)
            zp[b * H2 + j0 + jq * 4 + jj] = acc[i][jj];
    }
}

// ---------------------------------------------------------------------------
// Final: emb + head. one block per batch (64 x 320).
// ---------------------------------------------------------------------------
__global__ void final_kernel(const float* __restrict__ b2,
                             const float* __restrict__ W3,
                             const float* __restrict__ b3,
                             float* __restrict__ out) {
    const int b = blockIdx.x;
    const int k = threadIdx.x;            // 0..319
    const int gi = b * H2 + k;

    float z = 0.f;
#pragma unroll
    for (int s = 0; s < KS2; ++s) z += g_z2p[s][gi];
    float e = fmaxf(z + b2[k], 0.f);
    out[BATCH * 2 + gi] = e;

    float2 w = *reinterpret_cast<const float2*>(&W3[k * 2]);
    float p0 = e * w.x;
    float p1 = e * w.y;

#pragma unroll
    for (int off = 16; off > 0; off >>= 1) {
        p0 += __shfl_down_sync(0xFFFFFFFFu, p0, off);
        p1 += __shfl_down_sync(0xFFFFFFFFu, p1, off);
    }
    __shared__ float s0[10], s1[10];
    const int wid = k >> 5, lid = k & 31;
    if (lid == 0) { s0[wid] = p0; s1[wid] = p1; }
    __syncthreads();
    if (k == 0) {
        float a0 = 0.f, a1 = 0.f;
#pragma unroll
        for (int wi = 0; wi < 10; ++wi) { a0 += s0[wi]; a1 += s1[wi]; }
        out[b * 2 + 0] = a0 + b3[0];
        out[b * 2 + 1] = a1 + b3[1];
    }
}

// ---------------------------------------------------------------------------
extern "C" void kernel_launch(void* const* d_in, const int* in_sizes, int n_in,
                              void* d_out, int out_size) {
    const float* rep  = (const float*)d_in[0];
    const int*   blen = (const int*)  d_in[1];
    const float* W1   = (const float*)d_in[2];
    const float* b1   = (const float*)d_in[3];
    const float* W2   = (const float*)d_in[4];
    const float* b2   = (const float*)d_in[5];
    const float* W3   = (const float*)d_in[6];
    const float* b3   = (const float*)d_in[7];
    float* out = (float*)d_out;

    pool_kernel   <<<PGRID, 320>>>(rep, blen);
    reduce_kernel <<<BATCH, 320>>>(blen);
    gemm1_kernel  <<<dim3(H1 / JT, KS1), 128>>>(W1);
    relu_z1_kernel<<<(BATCH * H1) / 1024, 1024>>>(b1);
    gemm2_kernel  <<<dim3(H2 / JT, KS2), 128>>>(W2);
    final_kernel  <<<BATCH, H2>>>(b2, W3, b3, out);
}